// round 1
// baseline (speedup 1.0000x reference)
#include <cuda_runtime.h>
#include <math.h>

#define N_ITEMS 100000
#define E1N 400000
#define E2N 400000
#define DIM 128
#define N_TGT 40000
#define KC 32

// ---------------- scratch (static device globals; no runtime allocation) ----------------
__device__ float d_ft[(size_t)N_ITEMS * DIM];   // aggregated item features
__device__ float d_g [(size_t)N_ITEMS * DIM];   // ft @ W_q[:128]
__device__ float d_f [(size_t)N_TGT  * DIM];    // concat(h_t, last) @ W_r
__device__ float d_e1[E1N];
__device__ float d_ex[E1N];
__device__ int   d_menc[N_ITEMS];
__device__ float d_z [N_ITEMS];

// ---------------- helpers ----------------
__device__ __forceinline__ int fenc(float f) {
    int i = __float_as_int(f);
    return (i >= 0) ? i : (i ^ 0x7FFFFFFF);
}
__device__ __forceinline__ float fdec(int i) {
    return __int_as_float((i >= 0) ? i : (i ^ 0x7FFFFFFF));
}

__device__ __forceinline__ unsigned long long pack2(float lo, float hi) {
    unsigned long long r;
    asm("mov.b64 %0, {%1, %2};" : "=l"(r) : "f"(lo), "f"(hi));
    return r;
}
__device__ __forceinline__ void fma2(unsigned long long &d, unsigned long long a, unsigned long long b) {
    asm("fma.rn.f32x2 %0, %1, %2, %0;" : "+l"(d) : "l"(a), "l"(b));
}
__device__ __forceinline__ float2 unpack2(unsigned long long v) {
    float lo, hi;
    asm("mov.b64 {%0, %1}, %2;" : "=f"(lo), "=f"(hi) : "l"(v));
    return make_float2(lo, hi);
}
__device__ __forceinline__ void red_add_v4(float* p, float4 v) {
    asm volatile("red.global.add.v4.f32 [%0], {%1, %2, %3, %4};"
                 :: "l"(p), "f"(v.x), "f"(v.y), "f"(v.z), "f"(v.w) : "memory");
}

// ---------------- K0: init accumulators ----------------
__global__ void init_kernel(float* __restrict__ out) {
    int stride = gridDim.x * blockDim.x;
    int i0 = blockIdx.x * blockDim.x + threadIdx.x;
    for (int i = i0; i < N_ITEMS * DIM; i += stride) d_ft[i] = 0.0f;
    for (int i = i0; i < N_TGT * DIM;  i += stride) out[i]  = 0.0f;
    for (int i = i0; i < N_ITEMS;      i += stride) { d_z[i] = 0.0f; d_menc[i] = (int)0x80000000; }
}

// ---------------- K1: per-edge logit + segment max (warp per edge) ----------------
__global__ __launch_bounds__(256) void edge1_kernel(
    const float* __restrict__ h_v, const float* __restrict__ h_d,
    const float* __restrict__ W_pi, const float* __restrict__ W_M,
    const int* __restrict__ src1, const int* __restrict__ dst1)
{
    int wid = threadIdx.x >> 5, lane = threadIdx.x & 31;
    int e = blockIdx.x * 8 + wid;
    if (e >= E1N) return;
    int s = src1[e], d = dst1[e];
    float4 a  = ((const float4*)(h_v + (size_t)s * DIM))[lane];
    float4 b  = ((const float4*)(h_v + (size_t)d * DIM))[lane];
    float4 h  = ((const float4*)(h_d + (size_t)e * DIM))[lane];
    float4 p  = ((const float4*)W_pi)[lane];
    float4 ma = ((const float4*)W_M)[lane];
    float4 mb = ((const float4*)(W_M + DIM))[lane];
    float4 uv = make_float4(a.x*b.x, a.y*b.y, a.z*b.z, a.w*b.w);
    float d1 = uv.x*h.x*p.x + uv.y*h.y*p.y + uv.z*h.z*p.z + uv.w*h.w*p.w;
    float dm = uv.x*ma.x + uv.y*ma.y + uv.z*ma.z + uv.w*ma.w
             + h.x*mb.x + h.y*mb.y + h.z*mb.z + h.w*mb.w;
    #pragma unroll
    for (int o = 16; o; o >>= 1) {
        d1 += __shfl_xor_sync(0xffffffffu, d1, o);
        dm += __shfl_xor_sync(0xffffffffu, dm, o);
    }
    if (lane == 0) {
        float ev = d1 * (1.0f / (1.0f + expf(-dm)));
        d_e1[e] = ev;
        atomicMax(&d_menc[d], fenc(ev));
    }
}

// ---------------- K2: exp + segment sum (thread per edge) ----------------
__global__ void edge1_softmax_kernel(const int* __restrict__ dst1) {
    int e = blockIdx.x * blockDim.x + threadIdx.x;
    if (e >= E1N) return;
    int d = dst1[e];
    float m = fdec(d_menc[d]);
    float v = expf(d_e1[e] - m);
    d_ex[e] = v;
    atomicAdd(&d_z[d], v);
}

// ---------------- K3: normalize + aggregate ft (warp per edge) ----------------
__global__ __launch_bounds__(256) void edge1_agg_kernel(
    const float* __restrict__ h_v,
    const int* __restrict__ src1, const int* __restrict__ dst1)
{
    int wid = threadIdx.x >> 5, lane = threadIdx.x & 31;
    int e = blockIdx.x * 8 + wid;
    if (e >= E1N) return;
    int s = src1[e], d = dst1[e];
    float a = d_ex[e] / d_z[d];
    float4 v = ((const float4*)(h_v + (size_t)s * DIM))[lane];
    v.x *= a; v.y *= a; v.z *= a; v.w *= a;
    red_add_v4(d_ft + (size_t)d * DIM + lane * 4, v);
}

// ---------------- K4: g = ft @ W_q[:128]  (f32x2 register-tiled GEMM) ----------------
__global__ __launch_bounds__(256) void gemm_g_kernel(const float* __restrict__ W_q) {
    __shared__ __align__(16) float As[KC][132];
    __shared__ __align__(16) float Bs[KC][128];
    int tid = threadIdx.x;
    int ty = tid >> 4, tx = tid & 15;
    int rowBase = blockIdx.x * 128;
    unsigned long long acc[8][4];
    #pragma unroll
    for (int i = 0; i < 8; i++)
        #pragma unroll
        for (int j = 0; j < 4; j++) acc[i][j] = 0ULL;

    for (int k0 = 0; k0 < DIM; k0 += KC) {
        #pragma unroll
        for (int i = 0; i < 4; i++) {
            int lin = tid + i * 256;
            int r = lin >> 3, kq = lin & 7;
            int row = rowBase + r;
            float4 v = make_float4(0.f, 0.f, 0.f, 0.f);
            if (row < N_ITEMS) v = *(const float4*)&d_ft[(size_t)row * DIM + k0 + kq * 4];
            As[kq*4+0][r] = v.x; As[kq*4+1][r] = v.y; As[kq*4+2][r] = v.z; As[kq*4+3][r] = v.w;
        }
        #pragma unroll
        for (int i = 0; i < 4; i++) {
            int lin = tid + i * 256;
            int kk = lin >> 5, nq = lin & 31;
            *(float4*)&Bs[kk][nq*4] = *(const float4*)&W_q[(k0 + kk) * DIM + nq * 4];
        }
        __syncthreads();
        #pragma unroll
        for (int kk = 0; kk < KC; kk++) {
            float4 a0 = *(const float4*)&As[kk][ty*8];
            float4 a1 = *(const float4*)&As[kk][ty*8+4];
            ulonglong2 b0 = *(const ulonglong2*)&Bs[kk][tx*8];
            ulonglong2 b1 = *(const ulonglong2*)&Bs[kk][tx*8+4];
            float av[8] = {a0.x,a0.y,a0.z,a0.w,a1.x,a1.y,a1.z,a1.w};
            unsigned long long bp[4] = {b0.x, b0.y, b1.x, b1.y};
            #pragma unroll
            for (int i = 0; i < 8; i++) {
                unsigned long long ad = pack2(av[i], av[i]);
                #pragma unroll
                for (int j = 0; j < 4; j++) fma2(acc[i][j], ad, bp[j]);
            }
        }
        __syncthreads();
    }
    #pragma unroll
    for (int i = 0; i < 8; i++) {
        int row = rowBase + ty * 8 + i;
        if (row < N_ITEMS) {
            float o[8];
            #pragma unroll
            for (int j = 0; j < 4; j++) { float2 p2 = unpack2(acc[i][j]); o[2*j] = p2.x; o[2*j+1] = p2.y; }
            *(float4*)&d_g[(size_t)row * DIM + tx*8]     = make_float4(o[0], o[1], o[2], o[3]);
            *(float4*)&d_g[(size_t)row * DIM + tx*8 + 4] = make_float4(o[4], o[5], o[6], o[7]);
        }
    }
}

// ---------------- K5: f = concat(h_t, ft[last]) @ W_r  (gathered-A GEMM) ----------------
__global__ __launch_bounds__(256) void gemm_f_kernel(
    const float* __restrict__ h_t, const float* __restrict__ W_r,
    const int* __restrict__ last_idx)
{
    __shared__ __align__(16) float As[KC][132];
    __shared__ __align__(16) float Bs[KC][128];
    int tid = threadIdx.x;
    int ty = tid >> 4, tx = tid & 15;
    int rowBase = blockIdx.x * 128;
    unsigned long long acc[8][4];
    #pragma unroll
    for (int i = 0; i < 8; i++)
        #pragma unroll
        for (int j = 0; j < 4; j++) acc[i][j] = 0ULL;

    for (int k0 = 0; k0 < 2 * DIM; k0 += KC) {
        #pragma unroll
        for (int i = 0; i < 4; i++) {
            int lin = tid + i * 256;
            int r = lin >> 3, kq = lin & 7;
            int row = rowBase + r;
            float4 v = make_float4(0.f, 0.f, 0.f, 0.f);
            if (row < N_TGT) {
                if (k0 < DIM) {
                    v = *(const float4*)&h_t[(size_t)row * DIM + k0 + kq * 4];
                } else {
                    int li = last_idx[row >> 2];
                    v = *(const float4*)&d_ft[(size_t)li * DIM + (k0 - DIM) + kq * 4];
                }
            }
            As[kq*4+0][r] = v.x; As[kq*4+1][r] = v.y; As[kq*4+2][r] = v.z; As[kq*4+3][r] = v.w;
        }
        #pragma unroll
        for (int i = 0; i < 4; i++) {
            int lin = tid + i * 256;
            int kk = lin >> 5, nq = lin & 31;
            *(float4*)&Bs[kk][nq*4] = *(const float4*)&W_r[(k0 + kk) * DIM + nq * 4];
        }
        __syncthreads();
        #pragma unroll
        for (int kk = 0; kk < KC; kk++) {
            float4 a0 = *(const float4*)&As[kk][ty*8];
            float4 a1 = *(const float4*)&As[kk][ty*8+4];
            ulonglong2 b0 = *(const ulonglong2*)&Bs[kk][tx*8];
            ulonglong2 b1 = *(const ulonglong2*)&Bs[kk][tx*8+4];
            float av[8] = {a0.x,a0.y,a0.z,a0.w,a1.x,a1.y,a1.z,a1.w};
            unsigned long long bp[4] = {b0.x, b0.y, b1.x, b1.y};
            #pragma unroll
            for (int i = 0; i < 8; i++) {
                unsigned long long ad = pack2(av[i], av[i]);
                #pragma unroll
                for (int j = 0; j < 4; j++) fma2(acc[i][j], ad, bp[j]);
            }
        }
        __syncthreads();
    }
    #pragma unroll
    for (int i = 0; i < 8; i++) {
        int row = rowBase + ty * 8 + i;
        if (row < N_TGT) {
            float o[8];
            #pragma unroll
            for (int j = 0; j < 4; j++) { float2 p2 = unpack2(acc[i][j]); o[2*j] = p2.x; o[2*j+1] = p2.y; }
            *(float4*)&d_f[(size_t)row * DIM + tx*8]     = make_float4(o[0], o[1], o[2], o[3]);
            *(float4*)&d_f[(size_t)row * DIM + tx*8 + 4] = make_float4(o[4], o[5], o[6], o[7]);
        }
    }
}

// ---------------- K6: fused h_p@W_q[128:] + tanh + rowdot(f[dst2]) + scatter ----------------
__global__ __launch_bounds__(256) void edge2_kernel(
    const float* __restrict__ h_p, const float* __restrict__ W_q,
    const int* __restrict__ src2, const int* __restrict__ dst2,
    float* __restrict__ out)
{
    __shared__ __align__(16) float As[KC][132];
    __shared__ __align__(16) float Bs[KC][128];
    __shared__ int ssrc[128];
    __shared__ int sdst[128];
    __shared__ float s_s[128];
    int tid = threadIdx.x;
    int ty = tid >> 4, tx = tid & 15;
    int eb = blockIdx.x * 128;
    if (tid < 128) { ssrc[tid] = src2[eb + tid]; sdst[tid] = dst2[eb + tid]; }

    const float* Wb = W_q + DIM * DIM;   // bottom half rows [128:256)
    unsigned long long acc[8][4];
    #pragma unroll
    for (int i = 0; i < 8; i++)
        #pragma unroll
        for (int j = 0; j < 4; j++) acc[i][j] = 0ULL;

    for (int k0 = 0; k0 < DIM; k0 += KC) {
        #pragma unroll
        for (int i = 0; i < 4; i++) {
            int lin = tid + i * 256;
            int r = lin >> 3, kq = lin & 7;
            float4 v = *(const float4*)&h_p[(size_t)(eb + r) * DIM + k0 + kq * 4];
            As[kq*4+0][r] = v.x; As[kq*4+1][r] = v.y; As[kq*4+2][r] = v.z; As[kq*4+3][r] = v.w;
        }
        #pragma unroll
        for (int i = 0; i < 4; i++) {
            int lin = tid + i * 256;
            int kk = lin >> 5, nq = lin & 31;
            *(float4*)&Bs[kk][nq*4] = *(const float4*)&Wb[(k0 + kk) * DIM + nq * 4];
        }
        __syncthreads();
        #pragma unroll
        for (int kk = 0; kk < KC; kk++) {
            float4 a0 = *(const float4*)&As[kk][ty*8];
            float4 a1 = *(const float4*)&As[kk][ty*8+4];
            ulonglong2 b0 = *(const ulonglong2*)&Bs[kk][tx*8];
            ulonglong2 b1 = *(const ulonglong2*)&Bs[kk][tx*8+4];
            float av[8] = {a0.x,a0.y,a0.z,a0.w,a1.x,a1.y,a1.z,a1.w};
            unsigned long long bp[4] = {b0.x, b0.y, b1.x, b1.y};
            #pragma unroll
            for (int i = 0; i < 8; i++) {
                unsigned long long ad = pack2(av[i], av[i]);
                #pragma unroll
                for (int j = 0; j < 4; j++) fma2(acc[i][j], ad, bp[j]);
            }
        }
        __syncthreads();
    }

    // epilogue: e2 = tanh(acc + g[src2]); s = sum(e2 * f[dst2]) per edge row
    #pragma unroll
    for (int i = 0; i < 8; i++) {
        int r = ty * 8 + i;
        int sidx = ssrc[r], didx = sdst[r];
        const float4* gr = (const float4*)(d_g + (size_t)sidx * DIM);
        const float4* fr = (const float4*)(d_f + (size_t)didx * DIM);
        float4 g0 = gr[tx*2], g1 = gr[tx*2+1];
        float4 f0 = fr[tx*2], f1 = fr[tx*2+1];
        float q[8];
        #pragma unroll
        for (int j = 0; j < 4; j++) { float2 p2 = unpack2(acc[i][j]); q[2*j] = p2.x; q[2*j+1] = p2.y; }
        float s =
            tanhf(q[0] + g0.x) * f0.x + tanhf(q[1] + g0.y) * f0.y +
            tanhf(q[2] + g0.z) * f0.z + tanhf(q[3] + g0.w) * f0.w +
            tanhf(q[4] + g1.x) * f1.x + tanhf(q[5] + g1.y) * f1.y +
            tanhf(q[6] + g1.z) * f1.z + tanhf(q[7] + g1.w) * f1.w;
        #pragma unroll
        for (int o = 8; o; o >>= 1) s += __shfl_xor_sync(0xffffffffu, s, o);
        if (tx == 0) s_s[r] = s;
    }
    __syncthreads();

    // scatter: out[dst2[e]] += ft[src2[e]] * s[e]   (warp per row, coalesced red.v4)
    int wd = tid >> 5, lane = tid & 31;
    for (int r = wd * 16; r < wd * 16 + 16; r++) {
        float sv = s_s[r];
        float4 v = ((const float4*)(d_ft + (size_t)ssrc[r] * DIM))[lane];
        v.x *= sv; v.y *= sv; v.z *= sv; v.w *= sv;
        red_add_v4(out + (size_t)sdst[r] * DIM + lane * 4, v);
    }
}

// ---------------- launcher ----------------
extern "C" void kernel_launch(void* const* d_in, const int* in_sizes, int n_in,
                              void* d_out, int out_size) {
    const float* h_v  = (const float*)d_in[0];
    const float* h_d  = (const float*)d_in[1];
    const float* h_p  = (const float*)d_in[2];
    const float* h_t  = (const float*)d_in[3];
    const float* W_pi = (const float*)d_in[4];
    const float* W_M  = (const float*)d_in[5];
    const float* W_q  = (const float*)d_in[6];
    const float* W_r  = (const float*)d_in[7];
    const int* src1 = (const int*)d_in[8];
    const int* dst1 = (const int*)d_in[9];
    const int* src2 = (const int*)d_in[10];
    const int* dst2 = (const int*)d_in[11];
    const int* last_idx = (const int*)d_in[12];
    float* out = (float*)d_out;

    init_kernel<<<2048, 256>>>(out);
    edge1_kernel<<<(E1N + 7) / 8, 256>>>(h_v, h_d, W_pi, W_M, src1, dst1);
    edge1_softmax_kernel<<<(E1N + 255) / 256, 256>>>(dst1);
    edge1_agg_kernel<<<(E1N + 7) / 8, 256>>>(h_v, src1, dst1);
    gemm_g_kernel<<<(N_ITEMS + 127) / 128, 256>>>(W_q);
    gemm_f_kernel<<<(N_TGT + 127) / 128, 256>>>(h_t, W_r, last_idx);
    edge2_kernel<<<E2N / 128, 256>>>(h_p, W_q, src2, dst2, out);
}